// round 10
// baseline (speedup 1.0000x reference)
#include <cuda_runtime.h>
#include <cstdint>
#include <math.h>

#define B_   16
#define L_   128
#define H_   1024
#define V_   50257
#define LM1  127
#define VP   50264          // padded V (mult of 8)
#define NB2  393            // ceil(V/128) blocks for projection
#define KT2  128            // k-tile for h in K2
#define CW   3142           // 16 chunks cover V
#define CWP  3152           // padded chunk (mult of 16 floats)

// ---------------- scratch (device globals; no allocation allowed) ----------
__device__ __align__(16) float  g_x0[B_ * H_];
__device__ __align__(16) float  g_h0[B_ * H_];
__device__ __align__(16) float  g_h1t[H_ * B_];      // [k][b], b contiguous
__device__ __align__(16) float  g_logits[B_ * VP];   // logits + bias
__device__ __align__(16) float  g_bsum[400 * B_];    // per-block sum(exp)

// ---------------- K0a: x0 = relu(emb[tok]) ----------------------------------
__global__ void k0a_embed(const int* __restrict__ inp,
                          const float* __restrict__ emb) {
    int id = blockIdx.x * blockDim.x + threadIdx.x;   // 0..16383
    int b = id >> 10;
    int h = id & (H_ - 1);
    int tok = inp[b * L_];                            // input[b, 0]
    g_x0[id] = fmaxf(emb[(size_t)tok * H_ + h], 0.0f);
}

// ---------------- K0b: h0 = bridge ------------------------------------------
__global__ void k0b_bridge(const float* __restrict__ hidden,
                           const float* __restrict__ bw,
                           const float* __restrict__ bb) {
    int id = blockIdx.x * blockDim.x + threadIdx.x;   // 0..16383
    int b = id >> 10;
    int h = id & (H_ - 1);
    float acc = 0.0f;
    const float* hp = hidden + (size_t)b * L_ * H_ + h;
#pragma unroll 8
    for (int l = 0; l < L_; l++)
        acc += hp[(size_t)l * H_] * __ldg(bw + l);
    g_h0[id] = acc + __ldg(bb);
}

// ---------------- K1: GRU cell -> h1 (stored [k][b]) ------------------------
__global__ void k1_gates(const float* __restrict__ w_ih,
                         const float* __restrict__ w_hh,
                         const float* __restrict__ b_ih,
                         const float* __restrict__ b_hh) {
    __shared__ __align__(16) float sw[6 * H_];        // 24 KB: 6 weight rows
    int j = blockIdx.x;                               // output column 0..1023
    int tid = threadIdx.x;

    const float* rows[6];
    rows[0] = w_ih + (size_t)j * H_;
    rows[1] = w_ih + (size_t)(j + H_) * H_;
    rows[2] = w_ih + (size_t)(j + 2 * H_) * H_;
    rows[3] = w_hh + (size_t)j * H_;
    rows[4] = w_hh + (size_t)(j + H_) * H_;
    rows[5] = w_hh + (size_t)(j + 2 * H_) * H_;
#pragma unroll
    for (int r = 0; r < 6; r++) {
        float4* dst = (float4*)(sw + r * H_);
        const float4* src = (const float4*)rows[r];
#pragma unroll 2
        for (int i = tid; i < H_ / 4; i += 128)
            dst[i] = __ldg(src + i);
    }
    __syncthreads();

    int warp = tid >> 5, lane = tid & 31;
#define DOT4(acc, vv, ww) \
    acc += vv.x * ww.x + vv.y * ww.y + vv.z * ww.z + vv.w * ww.w
    for (int bb4 = 0; bb4 < 4; bb4++) {
        int b = warp * 4 + bb4;
        float a0 = 0, a1 = 0, a2 = 0, a3 = 0, a4 = 0, a5 = 0;
        const float* xp = g_x0 + b * H_;
        const float* hp = g_h0 + b * H_;
#pragma unroll
        for (int k = lane * 4; k < H_; k += 128) {
            float4 x = *(const float4*)(xp + k);
            float4 h = *(const float4*)(hp + k);
            float4 w0 = *(const float4*)(sw + k);
            float4 w1 = *(const float4*)(sw + H_ + k);
            float4 w2 = *(const float4*)(sw + 2 * H_ + k);
            float4 w3 = *(const float4*)(sw + 3 * H_ + k);
            float4 w4 = *(const float4*)(sw + 4 * H_ + k);
            float4 w5 = *(const float4*)(sw + 5 * H_ + k);
            DOT4(a0, x, w0); DOT4(a1, x, w1); DOT4(a2, x, w2);
            DOT4(a3, h, w3); DOT4(a4, h, w4); DOT4(a5, h, w5);
        }
#pragma unroll
        for (int off = 16; off; off >>= 1) {
            a0 += __shfl_xor_sync(0xffffffffu, a0, off);
            a1 += __shfl_xor_sync(0xffffffffu, a1, off);
            a2 += __shfl_xor_sync(0xffffffffu, a2, off);
            a3 += __shfl_xor_sync(0xffffffffu, a3, off);
            a4 += __shfl_xor_sync(0xffffffffu, a4, off);
            a5 += __shfl_xor_sync(0xffffffffu, a5, off);
        }
        if (lane == 0) {
            float ir = a0 + __ldg(b_ih + j);
            float iz = a1 + __ldg(b_ih + j + H_);
            float in_ = a2 + __ldg(b_ih + j + 2 * H_);
            float hr = a3 + __ldg(b_hh + j);
            float hz = a4 + __ldg(b_hh + j + H_);
            float hn = a5 + __ldg(b_hh + j + 2 * H_);
            float r = 1.0f / (1.0f + expf(-(ir + hr)));
            float z = 1.0f / (1.0f + expf(-(iz + hz)));
            float n = tanhf(in_ + r * hn);
            float h0v = g_h0[b * H_ + j];
            g_h1t[j * B_ + b] = (1.0f - z) * n + z * h0v;
        }
    }
#undef DOT4
}

// ---------------- K2: logits = h1 @ proj_w^T + b, sum-exp partials ----------
#define FMA2(acc, w2, h2) \
    asm("fma.rn.f32x2 %0, %1, %2, %0;" : "+l"(acc) : "l"(w2), "l"(h2))

__global__ void __launch_bounds__(128, 3)
k2_proj(const float* __restrict__ pw, const float* __restrict__ pb) {
    __shared__ __align__(16) float shh[KT2 * B_];    // 8 KB: h1 tile [k][b]
    __shared__ __align__(16) float shw[3][128 * 36]; // 55 KB ring of w tiles
    __shared__ float red[4][B_];

    int tid = threadIdx.x;
    int v = blockIdx.x * 128 + tid;
    bool active = (v < V_);
    int vc = active ? v : (V_ - 1);
    unsigned int shw_s0 = (unsigned int)__cvta_generic_to_shared(&shw[0][0]);

    // async-stage one 128x32 w tile (stage s covers k in [s*32, s*32+32))
    auto stage_load = [&](int s, int buf) {
        int kbase = s * 32;
        unsigned int base = shw_s0 + (unsigned int)buf * (128 * 36 * 4);
#pragma unroll
        for (int i2 = 0; i2 < 8; i2++) {
            int i = tid + 128 * i2;
            int r = i >> 3, c = i & 7;
            int vr = blockIdx.x * 128 + r;
            int vr2 = (vr < V_) ? vr : (V_ - 1);
            const float* src = pw + (size_t)vr2 * H_ + kbase + c * 4;
            int sz = (vr < V_) ? 16 : 0;
            unsigned int dst = base + (unsigned int)(r * 36 + c * 4) * 4;
            asm volatile("cp.async.cg.shared.global [%0], [%1], 16, %2;"
                         :: "r"(dst), "l"(src), "r"(sz));
        }
    };

    unsigned long long acc[8];
#pragma unroll
    for (int p = 0; p < 8; p++) acc[p] = 0ULL;

    stage_load(0, 0);
    asm volatile("cp.async.commit_group;");
    stage_load(1, 1);
    asm volatile("cp.async.commit_group;");

    for (int kt = 0; kt < 8; kt++) {
        for (int kwi = 0; kwi < 4; kwi++) {
            int s = kt * 4 + kwi;
            // hoist h loads (L2-resident) so their latency hides under the wait
            float4 h0r, h1r, h2r, h3r;
            if (kwi == 0) {
                const float4* src = (const float4*)(g_h1t + kt * KT2 * B_);
                h0r = src[tid];        h1r = src[tid + 128];
                h2r = src[tid + 256];  h3r = src[tid + 384];
            }
            if (s < 31)
                asm volatile("cp.async.wait_group 1;" ::: "memory");
            else
                asm volatile("cp.async.wait_group 0;" ::: "memory");
            __syncthreads();                // prev compute done, tile s ready
            if (s + 2 < 32) {               // prefetch 2 ahead into freed buffer
                stage_load(s + 2, (s + 2) % 3);
                asm volatile("cp.async.commit_group;");
            }
            if (kwi == 0) {                 // publish h tile for this kt
                float4* dst = (float4*)shh;
                dst[tid] = h0r;        dst[tid + 128] = h1r;
                dst[tid + 256] = h2r;  dst[tid + 384] = h3r;
                __syncthreads();
            }

            const ulonglong2* hb = (const ulonglong2*)(shh + (kwi * 32) * B_);
            const float4* wrow = (const float4*)&shw[s % 3][tid * 36];
#pragma unroll
            for (int c4i = 0; c4i < 8; c4i++) {
                float4 w4 = wrow[c4i];
#pragma unroll
                for (int j = 0; j < 4; j++) {
                    float wj = (j == 0) ? w4.x : (j == 1) ? w4.y
                             : (j == 2) ? w4.z : w4.w;
                    unsigned long long w2;
                    asm("mov.b64 %0, {%1, %1};" : "=l"(w2)
                        : "r"(__float_as_uint(wj)));
                    int k = c4i * 4 + j;
                    ulonglong2 pa = hb[k * 4 + 0];
                    ulonglong2 pq = hb[k * 4 + 1];
                    ulonglong2 pc = hb[k * 4 + 2];
                    ulonglong2 pd = hb[k * 4 + 3];
                    FMA2(acc[0], w2, pa.x); FMA2(acc[1], w2, pa.y);
                    FMA2(acc[2], w2, pq.x); FMA2(acc[3], w2, pq.y);
                    FMA2(acc[4], w2, pc.x); FMA2(acc[5], w2, pc.y);
                    FMA2(acc[6], w2, pd.x); FMA2(acc[7], w2, pd.y);
                }
            }
        }
    }

    float x[B_];
    float bias = __ldg(pb + vc);
#pragma unroll
    for (int p = 0; p < 8; p++) {
        unsigned int lo, hi;
        asm("mov.b64 {%0, %1}, %2;" : "=r"(lo), "=r"(hi) : "l"(acc[p]));
        x[2 * p]     = __uint_as_float(lo) + bias;
        x[2 * p + 1] = __uint_as_float(hi) + bias;
    }

    if (active) {
#pragma unroll
        for (int b = 0; b < B_; b++) g_logits[b * VP + v] = x[b];
    }

    // sum-exp partials (logits are small; no max subtraction needed)
    int lane = tid & 31, warp = tid >> 5;
#pragma unroll
    for (int b = 0; b < B_; b++) {
        float e = active ? __expf(x[b]) : 0.0f;
#pragma unroll
        for (int off = 16; off; off >>= 1)
            e += __shfl_xor_sync(0xffffffffu, e, off);
        if (lane == 0) red[warp][b] = e;
    }
    __syncthreads();
    if (tid < B_)
        g_bsum[blockIdx.x * B_ + tid] =
            red[0][tid] + red[1][tid] + red[2][tid] + red[3][tid];
}

// ---------------- K4: logZ prologue + TMA-bulk broadcast write ---------------
// grid = 16 b x 16 chunks x 4 t-quarters = 1024 blocks
__global__ void __launch_bounds__(256)
k4_bcast(float* __restrict__ out) {
    __shared__ __align__(16) float sh[CWP];
    __shared__ __align__(16) float shs[3][CWP];    // shifted by 1,2,3 floats
    __shared__ float wsum[8];
    __shared__ float slz;
    int tid = threadIdx.x;
    int b = blockIdx.x >> 6;
    int chunk = (blockIdx.x >> 2) & 15;
    int tq = blockIdx.x & 3;
    int c0 = chunk * CW;
    int cw = V_ - c0; if (cw > CW) cw = CW;
    int t0 = tq * 32;
    int t1 = t0 + 32; if (t1 > LM1) t1 = LM1;

    // deterministic logZ reduction over K2's per-block partials
    float s = 0.0f;
    for (int i = tid; i < NB2; i += 256) s += g_bsum[i * B_ + b];
#pragma unroll
    for (int off = 16; off; off >>= 1)
        s += __shfl_xor_sync(0xffffffffu, s, off);
    int lane = tid & 31, warp = tid >> 5;
    if (lane == 0) wsum[warp] = s;
    __syncthreads();
    if (tid == 0) {
        float t = 0.0f;
#pragma unroll
        for (int w = 0; w < 8; w++) t += wsum[w];
        slz = logf(t);
    }
    __syncthreads();
    float lz = slz;

    for (int i = tid; i < cw; i += 256)
        sh[i] = g_logits[b * VP + c0 + i] - lz;
    for (int i = cw + tid; i < CWP; i += 256)
        sh[i] = 0.0f;
    __syncthreads();
#pragma unroll
    for (int ss = 0; ss < 3; ss++)
        for (int i = tid; i + ss + 1 < CWP; i += 256)
            shs[ss][i] = sh[i + ss + 1];
    __syncthreads();
    asm volatile("fence.proxy.async.shared::cta;" ::: "memory");

    // rows round-robined over 8 warps; lane0 issues one bulk copy per row
    size_t base0 = (size_t)b * LM1 * V_ + c0;
    for (int t = t0 + warp; t < t1; t += 8) {
        size_t base = base0 + (size_t)t * V_;
        int a = (int)(base & 3);
        int head = (4 - a) & 3;
        int nf4 = (cw - head) >> 2;
        int done = head + 4 * nf4;
        int rem = cw - done;
        if (lane >= 1 && lane <= head)
            out[base + lane - 1] = sh[lane - 1];
        if (lane >= 4 && lane < 4 + rem)
            out[base + done + lane - 4] = sh[done + lane - 4];
        if (lane == 0) {
            const float* srcp = head ? shs[head - 1] : sh;
            unsigned int saddr = (unsigned int)__cvta_generic_to_shared(srcp);
            asm volatile(
                "cp.async.bulk.global.shared::cta.bulk_group [%0], [%1], %2;"
                :: "l"(out + base + head), "r"(saddr), "r"(nf4 * 16)
                : "memory");
        }
    }
    if (lane == 0) {
        asm volatile("cp.async.bulk.commit_group;" ::: "memory");
        asm volatile("cp.async.bulk.wait_group 0;" ::: "memory");
    }
}

// ---------------- launch -----------------------------------------------------
extern "C" void kernel_launch(void* const* d_in, const int* in_sizes, int n_in,
                              void* d_out, int out_size) {
    const int*   inp    = (const int*)d_in[0];
    const float* hidden = (const float*)d_in[1];
    const float* emb    = (const float*)d_in[2];
    const float* bw     = (const float*)d_in[3];
    const float* bb     = (const float*)d_in[4];
    const float* w_ih   = (const float*)d_in[5];
    const float* w_hh   = (const float*)d_in[6];
    const float* b_ih   = (const float*)d_in[7];
    const float* b_hh   = (const float*)d_in[8];
    const float* pw     = (const float*)d_in[9];
    const float* pb     = (const float*)d_in[10];
    float* out = (float*)d_out;

    k0a_embed<<<64, 256>>>(inp, emb);
    k0b_bridge<<<64, 256>>>(hidden, bw, bb);
    k1_gates<<<H_, 128>>>(w_ih, w_hh, b_ih, b_hh);
    k2_proj<<<NB2, 128>>>(pw, pb);          // <-- lands in ncu slot 6
    k4_bcast<<<16 * 16 * 4, 256>>>(out);
}

// round 11
// speedup vs baseline: 1.0985x; 1.0985x over previous
#include <cuda_runtime.h>
#include <cstdint>
#include <math.h>

#define B_   16
#define L_   128
#define H_   1024
#define V_   50257
#define LM1  127
#define VP   50264          // padded V (mult of 8)
#define NB2  393            // ceil(V/128) blocks for projection
#define CW   3142           // 16 chunks cover V
#define CWP  3152           // padded chunk (mult of 16 floats)

// ---------------- scratch (device globals; no allocation allowed) ----------
__device__ __align__(16) float  g_x0[B_ * H_];
__device__ __align__(16) float  g_h0[B_ * H_];
__device__ __align__(16) float  g_h1f[128 * 128];    // h1 in mma A-frag layout
__device__ __align__(16) float  g_logits[B_ * VP];   // logits + bias
__device__ __align__(16) float  g_bsum[400 * B_];    // per-block sum(exp)

// ---------------- K0a: x0 = relu(emb[tok]) ----------------------------------
__global__ void k0a_embed(const int* __restrict__ inp,
                          const float* __restrict__ emb) {
    int id = blockIdx.x * blockDim.x + threadIdx.x;   // 0..16383
    int b = id >> 10;
    int h = id & (H_ - 1);
    int tok = inp[b * L_];                            // input[b, 0]
    g_x0[id] = fmaxf(emb[(size_t)tok * H_ + h], 0.0f);
}

// ---------------- K0b: h0 = bridge ------------------------------------------
__global__ void k0b_bridge(const float* __restrict__ hidden,
                           const float* __restrict__ bw,
                           const float* __restrict__ bb) {
    int id = blockIdx.x * blockDim.x + threadIdx.x;   // 0..16383
    int b = id >> 10;
    int h = id & (H_ - 1);
    float acc = 0.0f;
    const float* hp = hidden + (size_t)b * L_ * H_ + h;
#pragma unroll 8
    for (int l = 0; l < L_; l++)
        acc += hp[(size_t)l * H_] * __ldg(bw + l);
    g_h0[id] = acc + __ldg(bb);
}

// ---------------- K1: GRU cell -> h1 (stored as tf32 A-fragments) -----------
__global__ void k1_gates(const float* __restrict__ w_ih,
                         const float* __restrict__ w_hh,
                         const float* __restrict__ b_ih,
                         const float* __restrict__ b_hh) {
    __shared__ __align__(16) float sw[6 * H_];        // 24 KB: 6 weight rows
    int j = blockIdx.x;                               // output column 0..1023
    int tid = threadIdx.x;

    const float* rows[6];
    rows[0] = w_ih + (size_t)j * H_;
    rows[1] = w_ih + (size_t)(j + H_) * H_;
    rows[2] = w_ih + (size_t)(j + 2 * H_) * H_;
    rows[3] = w_hh + (size_t)j * H_;
    rows[4] = w_hh + (size_t)(j + H_) * H_;
    rows[5] = w_hh + (size_t)(j + 2 * H_) * H_;
#pragma unroll
    for (int r = 0; r < 6; r++) {
        float4* dst = (float4*)(sw + r * H_);
        const float4* src = (const float4*)rows[r];
#pragma unroll 2
        for (int i = tid; i < H_ / 4; i += 128)
            dst[i] = __ldg(src + i);
    }
    __syncthreads();

    int warp = tid >> 5, lane = tid & 31;
#define DOT4(acc, vv, ww) \
    acc += vv.x * ww.x + vv.y * ww.y + vv.z * ww.z + vv.w * ww.w
    for (int bb4 = 0; bb4 < 4; bb4++) {
        int b = warp * 4 + bb4;
        float a0 = 0, a1 = 0, a2 = 0, a3 = 0, a4 = 0, a5 = 0;
        const float* xp = g_x0 + b * H_;
        const float* hp = g_h0 + b * H_;
#pragma unroll
        for (int k = lane * 4; k < H_; k += 128) {
            float4 x = *(const float4*)(xp + k);
            float4 h = *(const float4*)(hp + k);
            float4 w0 = *(const float4*)(sw + k);
            float4 w1 = *(const float4*)(sw + H_ + k);
            float4 w2 = *(const float4*)(sw + 2 * H_ + k);
            float4 w3 = *(const float4*)(sw + 3 * H_ + k);
            float4 w4 = *(const float4*)(sw + 4 * H_ + k);
            float4 w5 = *(const float4*)(sw + 5 * H_ + k);
            DOT4(a0, x, w0); DOT4(a1, x, w1); DOT4(a2, x, w2);
            DOT4(a3, h, w3); DOT4(a4, h, w4); DOT4(a5, h, w5);
        }
#pragma unroll
        for (int off = 16; off; off >>= 1) {
            a0 += __shfl_xor_sync(0xffffffffu, a0, off);
            a1 += __shfl_xor_sync(0xffffffffu, a1, off);
            a2 += __shfl_xor_sync(0xffffffffu, a2, off);
            a3 += __shfl_xor_sync(0xffffffffu, a3, off);
            a4 += __shfl_xor_sync(0xffffffffu, a4, off);
            a5 += __shfl_xor_sync(0xffffffffu, a5, off);
        }
        if (lane == 0) {
            float ir = a0 + __ldg(b_ih + j);
            float iz = a1 + __ldg(b_ih + j + H_);
            float in_ = a2 + __ldg(b_ih + j + 2 * H_);
            float hr = a3 + __ldg(b_hh + j);
            float hz = a4 + __ldg(b_hh + j + H_);
            float hn = a5 + __ldg(b_hh + j + 2 * H_);
            float r = 1.0f / (1.0f + expf(-(ir + hr)));
            float z = 1.0f / (1.0f + expf(-(iz + hz)));
            float n = tanhf(in_ + r * hn);
            float h0v = g_h0[b * H_ + j];
            float h1 = (1.0f - z) * n + z * h0v;
            // store in m16n8k8 A-fragment layout, rounded to tf32
            unsigned int tv;
            asm("cvt.rna.tf32.f32 %0, %1;" : "=r"(tv) : "f"(h1));
            int s = j >> 3;                       // kstep
            int lf = ((b & 7) << 2) | (j & 3);    // lane
            int rr = (b >> 3) + (((j >> 2) & 1) << 1);  // reg
            g_h1f[s * 128 + lf * 4 + rr] = __uint_as_float(tv);
        }
    }
#undef DOT4
}

// ---------------- K2: logits = h1 @ proj_w^T + b via mma.tf32 ---------------
__global__ void __launch_bounds__(128, 4)
k2_proj(const float* __restrict__ pw, const float* __restrict__ pb) {
    __shared__ __align__(16) float shw[2][128 * 36]; // 36.9 KB w ring
    __shared__ __align__(16) float sha[2048];        // 8 KB A frags (one kt)
    __shared__ float red[4][B_];

    int tid = threadIdx.x;
    int warp = tid >> 5, lane = tid & 31;
    unsigned int shw_s0 = (unsigned int)__cvta_generic_to_shared(&shw[0][0]);

    // async-stage one 128x32 w tile (stage s covers k in [s*32, s*32+32))
    auto stage_load = [&](int s) {
        int kbase = s * 32;
        unsigned int base = shw_s0 + (unsigned int)(s & 1) * (128 * 36 * 4);
#pragma unroll
        for (int i2 = 0; i2 < 8; i2++) {
            int i = tid + 128 * i2;
            int r = i >> 3, c = i & 7;
            int vr = blockIdx.x * 128 + r;
            int vr2 = (vr < V_) ? vr : (V_ - 1);
            const float* src = pw + (size_t)vr2 * H_ + kbase + c * 4;
            int sz = (vr < V_) ? 16 : 0;
            unsigned int dst = base + (unsigned int)(r * 36 + c * 4) * 4;
            asm volatile("cp.async.cg.shared.global [%0], [%1], 16, %2;"
                         :: "r"(dst), "l"(src), "r"(sz));
        }
    };

    float d[4][4];
#pragma unroll
    for (int nt = 0; nt < 4; nt++)
#pragma unroll
        for (int p = 0; p < 4; p++) d[nt][p] = 0.0f;

    stage_load(0);
    asm volatile("cp.async.commit_group;");

    int rbase = warp * 32 + (lane >> 2);
    int cbase = lane & 3;

    for (int s = 0; s < 32; s++) {
        float4 af0, af1, af2, af3;
        if ((s & 3) == 0) {                 // hoist A loads (L2) over the wait
            const float4* asrc = (const float4*)(g_h1f + (s >> 2) * 2048);
            af0 = asrc[tid];       af1 = asrc[tid + 128];
            af2 = asrc[tid + 256]; af3 = asrc[tid + 384];
        }
        asm volatile("cp.async.wait_group 0;" ::: "memory");
        __syncthreads();                    // tile s ready, prev compute done
        if (s + 1 < 32) {
            stage_load(s + 1);
            asm volatile("cp.async.commit_group;");
        }
        if ((s & 3) == 0) {                 // publish A frags for this kt
            float4* ad = (float4*)sha;
            ad[tid] = af0;       ad[tid + 128] = af1;
            ad[tid + 256] = af2; ad[tid + 384] = af3;
            __syncthreads();
        }

        const float* wb = shw[s & 1];
#pragma unroll
        for (int q = 0; q < 4; q++) {
            int sl = (s & 3) * 4 + q;
            float4 av = *(const float4*)(sha + sl * 128 + lane * 4);
            unsigned int a0 = __float_as_uint(av.x), a1 = __float_as_uint(av.y);
            unsigned int a2 = __float_as_uint(av.z), a3 = __float_as_uint(av.w);
#pragma unroll
            for (int nt = 0; nt < 4; nt++) {
                const float* wr = wb + (rbase + nt * 8) * 36 + q * 8 + cbase;
                unsigned int b0 = __float_as_uint(wr[0]);
                unsigned int b1 = __float_as_uint(wr[4]);
                asm volatile(
                    "mma.sync.aligned.m16n8k8.row.col.f32.tf32.tf32.f32 "
                    "{%0,%1,%2,%3}, {%4,%5,%6,%7}, {%8,%9}, {%0,%1,%2,%3};"
                    : "+f"(d[nt][0]), "+f"(d[nt][1]),
                      "+f"(d[nt][2]), "+f"(d[nt][3])
                    : "r"(a0), "r"(a1), "r"(a2), "r"(a3), "r"(b0), "r"(b1));
            }
        }
    }

    // epilogue: bias, store logits, per-block sum(exp) partials
    float slo = 0.0f, shi = 0.0f;
    int vb = blockIdx.x * 128 + warp * 32;
    int blo = lane >> 2;
#pragma unroll
    for (int nt = 0; nt < 4; nt++) {
        int v0 = vb + nt * 8 + (lane & 3) * 2;
        int v1 = v0 + 1;
        float bi0 = __ldg(pb + (v0 < V_ ? v0 : V_ - 1));
        float bi1 = __ldg(pb + (v1 < V_ ? v1 : V_ - 1));
        float x0 = d[nt][0] + bi0, x1 = d[nt][1] + bi1;
        float x2 = d[nt][2] + bi0, x3 = d[nt][3] + bi1;
        if (v0 < V_) {
            g_logits[blo * VP + v0] = x0;
            g_logits[(blo + 8) * VP + v0] = x2;
            slo += __expf(x0); shi += __expf(x2);
        }
        if (v1 < V_) {
            g_logits[blo * VP + v1] = x1;
            g_logits[(blo + 8) * VP + v1] = x3;
            slo += __expf(x1); shi += __expf(x3);
        }
    }
    slo += __shfl_xor_sync(0xffffffffu, slo, 1);
    slo += __shfl_xor_sync(0xffffffffu, slo, 2);
    shi += __shfl_xor_sync(0xffffffffu, shi, 1);
    shi += __shfl_xor_sync(0xffffffffu, shi, 2);
    if ((lane & 3) == 0) {
        red[warp][blo] = slo;
        red[warp][blo + 8] = shi;
    }
    __syncthreads();
    if (tid < B_)
        g_bsum[blockIdx.x * B_ + tid] =
            red[0][tid] + red[1][tid] + red[2][tid] + red[3][tid];
}

// ---------------- K4: logZ prologue + TMA-bulk broadcast write ---------------
// grid = 16 b x 16 chunks x 4 t-quarters = 1024 blocks
__global__ void __launch_bounds__(256)
k4_bcast(float* __restrict__ out) {
    __shared__ __align__(16) float sh[CWP];
    __shared__ __align__(16) float shs[3][CWP];    // shifted by 1,2,3 floats
    __shared__ float wsum[8];
    __shared__ float slz;
    int tid = threadIdx.x;
    int b = blockIdx.x >> 6;
    int chunk = (blockIdx.x >> 2) & 15;
    int tq = blockIdx.x & 3;
    int c0 = chunk * CW;
    int cw = V_ - c0; if (cw > CW) cw = CW;
    int t0 = tq * 32;
    int t1 = t0 + 32; if (t1 > LM1) t1 = LM1;

    // deterministic logZ reduction over K2's per-block partials
    float s = 0.0f;
    for (int i = tid; i < NB2; i += 256) s += g_bsum[i * B_ + b];
#pragma unroll
    for (int off = 16; off; off >>= 1)
        s += __shfl_xor_sync(0xffffffffu, s, off);
    int lane = tid & 31, warp = tid >> 5;
    if (lane == 0) wsum[warp] = s;
    __syncthreads();
    if (tid == 0) {
        float t = 0.0f;
#pragma unroll
        for (int w = 0; w < 8; w++) t += wsum[w];
        slz = logf(t);
    }
    __syncthreads();
    float lz = slz;

    for (int i = tid; i < cw; i += 256)
        sh[i] = g_logits[b * VP + c0 + i] - lz;
    for (int i = cw + tid; i < CWP; i += 256)
        sh[i] = 0.0f;
    __syncthreads();
#pragma unroll
    for (int ss = 0; ss < 3; ss++)
        for (int i = tid; i + ss + 1 < CWP; i += 256)
            shs[ss][i] = sh[i + ss + 1];
    __syncthreads();
    asm volatile("fence.proxy.async.shared::cta;" ::: "memory");

    // rows round-robined over 8 warps; lane0 issues one bulk copy per row
    size_t base0 = (size_t)b * LM1 * V_ + c0;
    for (int t = t0 + warp; t < t1; t += 8) {
        size_t base = base0 + (size_t)t * V_;
        int a = (int)(base & 3);
        int head = (4 - a) & 3;
        int nf4 = (cw - head) >> 2;
        int done = head + 4 * nf4;
        int rem = cw - done;
        if (lane >= 1 && lane <= head)
            out[base + lane - 1] = sh[lane - 1];
        if (lane >= 4 && lane < 4 + rem)
            out[base + done + lane - 4] = sh[done + lane - 4];
        if (lane == 0) {
            const float* srcp = head ? shs[head - 1] : sh;
            unsigned int saddr = (unsigned int)__cvta_generic_to_shared(srcp);
            asm volatile(
                "cp.async.bulk.global.shared::cta.bulk_group [%0], [%1], %2;"
                :: "l"(out + base + head), "r"(saddr), "r"(nf4 * 16)
                : "memory");
        }
    }
    if (lane == 0) {
        asm volatile("cp.async.bulk.commit_group;" ::: "memory");
        asm volatile("cp.async.bulk.wait_group 0;" ::: "memory");
    }
}

// ---------------- launch -----------------------------------------------------
extern "C" void kernel_launch(void* const* d_in, const int* in_sizes, int n_in,
                              void* d_out, int out_size) {
    const int*   inp    = (const int*)d_in[0];
    const float* hidden = (const float*)d_in[1];
    const float* emb    = (const float*)d_in[2];
    const float* bw     = (const float*)d_in[3];
    const float* bb     = (const float*)d_in[4];
    const float* w_ih   = (const float*)d_in[5];
    const float* w_hh   = (const float*)d_in[6];
    const float* b_ih   = (const float*)d_in[7];
    const float* b_hh   = (const float*)d_in[8];
    const float* pw     = (const float*)d_in[9];
    const float* pb     = (const float*)d_in[10];
    float* out = (float*)d_out;

    k0a_embed<<<64, 256>>>(inp, emb);
    k0b_bridge<<<64, 256>>>(hidden, bw, bb);
    k1_gates<<<H_, 128>>>(w_ih, w_hh, b_ih, b_hh);
    k2_proj<<<NB2, 128>>>(pw, pb);          // <-- lands in ncu slot 6
    k4_bcast<<<16 * 16 * 4, 256>>>(out);
}